// round 1
// baseline (speedup 1.0000x reference)
#include <cuda_runtime.h>

// Problem constants
#define BB 128   // batch
#define TT 128   // timesteps
#define NN 100   // subactors
#define HH 16    // hidden
#define SS 6     // state
#define GG 48    // 3*H gates
#define GP 24    // gate pairs
#define HP 8     // hidden pairs

typedef unsigned long long ull;

// ---- packed f32x2 helpers (sm_100+; ptxas never auto-fuses these) ----
__device__ __forceinline__ ull ffma2(ull a, ull b, ull c) {
    ull d; asm("fma.rn.f32x2 %0, %1, %2, %3;" : "=l"(d) : "l"(a), "l"(b), "l"(c)); return d;
}
__device__ __forceinline__ ull fadd2(ull a, ull b) {
    ull d; asm("add.rn.f32x2 %0, %1, %2;" : "=l"(d) : "l"(a), "l"(b)); return d;
}
__device__ __forceinline__ ull pack2(float lo, float hi) {
    ull r; asm("mov.b64 %0, {%1, %2};" : "=l"(r) : "f"(lo), "f"(hi)); return r;
}
__device__ __forceinline__ float2 unpack2(ull v) {
    float2 f; asm("mov.b64 {%0, %1}, %2;" : "=f"(f.x), "=f"(f.y) : "l"(v)); return f;
}
// ---- fast activations (MUFU-based, ~1e-6 rel err, safe for 1e-3 threshold) ----
__device__ __forceinline__ float fex2(float x) { float y; asm("ex2.approx.f32 %0, %1;" : "=f"(y) : "f"(x)); return y; }
__device__ __forceinline__ float frcp(float x) { float y; asm("rcp.approx.f32 %0, %1;" : "=f"(y) : "f"(x)); return y; }
__device__ __forceinline__ float fsigmoid(float x) {
    // 1/(1+e^{-x}) ; large |x| saturates correctly via inf/0 paths
    return frcp(1.0f + fex2(-1.4426950408889634f * x));
}
__device__ __forceinline__ float ftanh_(float x) {
    // 1 - 2/(e^{2x}+1)
    return fmaf(-2.0f, frcp(1.0f + fex2(2.8853900817779268f * x)), 1.0f);
}

__global__ void __launch_bounds__(BB)
actor_fused_kernel(const float* __restrict__ x,
                   const float* __restrict__ Wih, const float* __restrict__ Whh,
                   const float* __restrict__ bih, const float* __restrict__ bhh,
                   const float* __restrict__ W1,  const float* __restrict__ b1,
                   const float* __restrict__ W2,  const float* __restrict__ b2,
                   const float* __restrict__ W3,  const float* __restrict__ b3,
                   float* __restrict__ out)
{
    const int n   = blockIdx.x;    // subactor
    const int b   = threadIdx.x;   // batch element (one sequence per thread)
    const int tid = threadIdx.x;

    // Weights in smem, packed as f32x2 pairs along the OUTPUT dimension so the
    // inner K-loop broadcasts a duplicated scalar against packed weight pairs.
    __shared__ ull sWhh[HH][GP];   // [k=j][pair over gates]
    __shared__ ull sWih[SS][GP];   // [k=s][pair over gates]
    __shared__ ull sBih[GP], sBhh[GP];
    __shared__ ull sW1[HH][HP];    // [k=j][pair over out units]
    __shared__ ull sW2[HH][HP];
    __shared__ ull sW3[HP];        // pairs over K (horizontal reduce at end)
    __shared__ ull sB1[HP], sB2[HP];
    __shared__ float sB3;

    for (int idx = tid; idx < HH * GP; idx += BB) {
        int j = idx / GP, p = idx % GP;
        sWhh[j][p] = pack2(Whh[(n * GG + 2 * p) * HH + j], Whh[(n * GG + 2 * p + 1) * HH + j]);
    }
    for (int idx = tid; idx < SS * GP; idx += BB) {
        int s = idx / GP, p = idx % GP;
        sWih[s][p] = pack2(Wih[(n * GG + 2 * p) * SS + s], Wih[(n * GG + 2 * p + 1) * SS + s]);
    }
    for (int idx = tid; idx < GP; idx += BB) {
        sBih[idx] = pack2(bih[n * GG + 2 * idx], bih[n * GG + 2 * idx + 1]);
        sBhh[idx] = pack2(bhh[n * GG + 2 * idx], bhh[n * GG + 2 * idx + 1]);
    }
    for (int idx = tid; idx < HH * HP; idx += BB) {
        int j = idx / HP, p = idx % HP;
        sW1[j][p] = pack2(W1[(n * HH + 2 * p) * HH + j], W1[(n * HH + 2 * p + 1) * HH + j]);
        sW2[j][p] = pack2(W2[(n * HH + 2 * p) * HH + j], W2[(n * HH + 2 * p + 1) * HH + j]);
    }
    for (int idx = tid; idx < HP; idx += BB) {
        sW3[idx] = pack2(W3[n * HH + 2 * idx], W3[n * HH + 2 * idx + 1]);
        sB1[idx] = pack2(b1[n * HH + 2 * idx], b1[n * HH + 2 * idx + 1]);
        sB2[idx] = pack2(b2[n * HH + 2 * idx], b2[n * HH + 2 * idx + 1]);
    }
    if (tid == 0) sB3 = b3[n];
    __syncthreads();

    // GRU hidden state: scalars + duplicated-pair mirrors for broadcast FMAs
    float h[HH];
    ull   hd[HH];
#pragma unroll
    for (int j = 0; j < HH; j++) { h[j] = 0.0f; hd[j] = 0ULL; }

    // x[b][t][n][s] : stride per t = N*S = 600 floats; 24B-aligned -> float2 ok
    const float* xp = x + (long long)b * TT * NN * SS + n * SS;
    float* op = out + n * (BB * TT) + b * TT;   // out[n*B*T + b*T + t]
    float ybuf[4];

#pragma unroll 1
    for (int t = 0; t < TT; t++) {
        // --- load x_t (6 floats) early; hh compute below hides L2 latency ---
        float2 xv0 = *reinterpret_cast<const float2*>(xp);
        float2 xv1 = *reinterpret_cast<const float2*>(xp + 2);
        float2 xv2 = *reinterpret_cast<const float2*>(xp + 4);
        xp += NN * SS;

        // --- hh = h @ Whh^T + bhh  (packed pairs over 48 gates) ---
        ull hh2[GP];
#pragma unroll
        for (int p = 0; p < GP; p++) hh2[p] = sBhh[p];
#pragma unroll
        for (int j = 0; j < HH; j++) {
#pragma unroll
            for (int p = 0; p < GP; p++) hh2[p] = ffma2(hd[j], sWhh[j][p], hh2[p]);
        }

        // --- xi = x_t @ Wih^T + bih ---
        ull xi2[GP];
#pragma unroll
        for (int p = 0; p < GP; p++) xi2[p] = sBih[p];
        {
            float xs0 = xv0.x, xs1 = xv0.y, xs2 = xv1.x, xs3 = xv1.y, xs4 = xv2.x, xs5 = xv2.y;
            ull xd;
            xd = pack2(xs0, xs0);
#pragma unroll
            for (int p = 0; p < GP; p++) xi2[p] = ffma2(xd, sWih[0][p], xi2[p]);
            xd = pack2(xs1, xs1);
#pragma unroll
            for (int p = 0; p < GP; p++) xi2[p] = ffma2(xd, sWih[1][p], xi2[p]);
            xd = pack2(xs2, xs2);
#pragma unroll
            for (int p = 0; p < GP; p++) xi2[p] = ffma2(xd, sWih[2][p], xi2[p]);
            xd = pack2(xs3, xs3);
#pragma unroll
            for (int p = 0; p < GP; p++) xi2[p] = ffma2(xd, sWih[3][p], xi2[p]);
            xd = pack2(xs4, xs4);
#pragma unroll
            for (int p = 0; p < GP; p++) xi2[p] = ffma2(xd, sWih[4][p], xi2[p]);
            xd = pack2(xs5, xs5);
#pragma unroll
            for (int p = 0; p < GP; p++) xi2[p] = ffma2(xd, sWih[5][p], xi2[p]);
        }

        // --- gates + state update (torch order r,z,n: pairs 0-7 / 8-15 / 16-23) ---
#pragma unroll
        for (int u = 0; u < 8; u++) {
            float2 ar = unpack2(fadd2(xi2[u],      hh2[u]));
            float2 az = unpack2(fadd2(xi2[u + 8],  hh2[u + 8]));
            float2 xn = unpack2(xi2[u + 16]);
            float2 hn = unpack2(hh2[u + 16]);
            float r0 = fsigmoid(ar.x), r1 = fsigmoid(ar.y);
            float z0 = fsigmoid(az.x), z1 = fsigmoid(az.y);
            float n0 = ftanh_(fmaf(r0, hn.x, xn.x));
            float n1 = ftanh_(fmaf(r1, hn.y, xn.y));
            int j0 = 2 * u, j1 = 2 * u + 1;
            // hnew = (1-z)*n + z*h = z*(h-n) + n
            h[j0] = fmaf(z0, h[j0] - n0, n0);
            h[j1] = fmaf(z1, h[j1] - n1, n1);
            hd[j0] = pack2(h[j0], h[j0]);
            hd[j1] = pack2(h[j1], h[j1]);
        }

        // --- MLP head: relu(W1 h + b1) -> relu(W2 . + b2) -> relu(W3 . + b3) ---
        ull a1[HP];
#pragma unroll
        for (int p = 0; p < HP; p++) a1[p] = sB1[p];
#pragma unroll
        for (int j = 0; j < HH; j++) {
#pragma unroll
            for (int p = 0; p < HP; p++) a1[p] = ffma2(hd[j], sW1[j][p], a1[p]);
        }
        ull y1d[HH];
#pragma unroll
        for (int p = 0; p < HP; p++) {
            float2 v = unpack2(a1[p]);
            float va = fmaxf(v.x, 0.0f), vb = fmaxf(v.y, 0.0f);
            y1d[2 * p]     = pack2(va, va);
            y1d[2 * p + 1] = pack2(vb, vb);
        }
        ull a2[HP];
#pragma unroll
        for (int p = 0; p < HP; p++) a2[p] = sB2[p];
#pragma unroll
        for (int j = 0; j < HH; j++) {
#pragma unroll
            for (int p = 0; p < HP; p++) a2[p] = ffma2(y1d[j], sW2[j][p], a2[p]);
        }
        ull acc = 0ULL;
#pragma unroll
        for (int p = 0; p < HP; p++) {
            float2 v = unpack2(a2[p]);
            ull y2p = pack2(fmaxf(v.x, 0.0f), fmaxf(v.y, 0.0f));
            acc = ffma2(y2p, sW3[p], acc);
        }
        float2 av = unpack2(acc);
        ybuf[t & 3] = fmaxf(av.x + av.y + sB3, 0.0f);

        if ((t & 3) == 3) {
            *reinterpret_cast<float4*>(op + t - 3) =
                make_float4(ybuf[0], ybuf[1], ybuf[2], ybuf[3]);
        }
    }
}

extern "C" void kernel_launch(void* const* d_in, const int* in_sizes, int n_in,
                              void* d_out, int out_size)
{
    (void)in_sizes; (void)n_in; (void)out_size;
    const float* x   = (const float*)d_in[0];
    const float* Wih = (const float*)d_in[1];
    const float* Whh = (const float*)d_in[2];
    const float* bih = (const float*)d_in[3];
    const float* bhh = (const float*)d_in[4];
    const float* W1  = (const float*)d_in[5];
    const float* b1  = (const float*)d_in[6];
    const float* W2  = (const float*)d_in[7];
    const float* b2  = (const float*)d_in[8];
    const float* W3  = (const float*)d_in[9];
    const float* b3  = (const float*)d_in[10];
    float* out = (float*)d_out;

    actor_fused_kernel<<<NN, BB>>>(x, Wih, Whh, bih, bhh, W1, b1, W2, b2, W3, b3, out);
}